// round 7
// baseline (speedup 1.0000x reference)
#include <cuda_runtime.h>
#include <math_constants.h>

#define NROWS 2048
#define DIM   1024
#define KCENT 256
#define NB    1024
#define TPB   256

__device__ float2 g_tab[KCENT];    // (midpoint, centroid); mid[255] = +inf
__device__ float2 g_lutf[NB];      // per-bin (mid[i], cen[i]) at i = lowerbound
__device__ int    g_luti[NB];      // per-bin lowerbound index
__device__ float  g_sb[2];         // scale, bias
__device__ float  g_norm[NROWS];   // per-row norms

// ---------------- prep: build tables once (1 CTA) ----------------
__global__ __launch_bounds__(256)
void prep_kernel(const float* __restrict__ centroids) {
    __shared__ float smid[KCENT];
    __shared__ float scen[KCENT];
    __shared__ int   lut[NB];
    __shared__ int   swsum[8];

    const int t    = threadIdx.x;
    const int lane = t & 31;
    const int wid  = t >> 5;

    const float c0 = centroids[t];
    const float c1 = centroids[t < KCENT - 1 ? t + 1 : KCENT - 1];
    const float mid = (t < KCENT - 1) ? 0.5f * (c0 + c1) : CUDART_INF_F;
    smid[t] = mid;
    scen[t] = c0;
    g_tab[t] = make_float2(mid, c0);
    reinterpret_cast<int4*>(lut)[t] = make_int4(0, 0, 0, 0);
    __syncthreads();

    const float lo    = smid[0];
    const float hi    = smid[KCENT - 2];
    const float scale = (float)NB / fmaxf(hi - lo, 1e-30f);
    const float bias  = -lo * scale;
    if (t == 0) { g_sb[0] = scale; g_sb[1] = bias; }

    if (t < KCENT - 1) {
        float bf = fmaf(mid, scale, bias);
        int b = (int)fminf(fmaxf(bf, 0.0f), (float)(NB - 1));
        atomicAdd(&lut[b], 1);
    }
    __syncthreads();

    // exclusive prefix scan over NB bins (4 bins/thread)
    int4 h = reinterpret_cast<int4*>(lut)[t];
    const int hsum = h.x + h.y + h.z + h.w;
    int inc = hsum;
    #pragma unroll
    for (int o = 1; o < 32; o <<= 1) {
        int n = __shfl_up_sync(0xffffffffu, inc, o);
        if (lane >= o) inc += n;
    }
    if (lane == 31) swsum[wid] = inc;
    __syncthreads();

    int base = inc - hsum;
    #pragma unroll
    for (int i = 0; i < 8; i++)
        if (i < wid) base += swsum[i];

    int4 e;
    e.x = base;
    e.y = e.x + h.x;  e.z = e.y + h.y;  e.w = e.z + h.z;
    reinterpret_cast<int4*>(g_luti)[t] = e;

    // per-bin fast-path payloads (4 bins/thread)
    #pragma unroll
    for (int j = 0; j < 4; j++) {
        int b   = 4 * t + j;
        int idx = (&e.x)[j];
        g_lutf[b] = make_float2(smid[idx], scen[idx]);
    }
}

// ---------------- norms: warp per row, no barriers ----------------
__global__ __launch_bounds__(256)
void norm_kernel(const float* __restrict__ x) {
    const int lane = threadIdx.x & 31;
    const int row  = (blockIdx.x * 256 + threadIdx.x) >> 5;
    const float4* __restrict__ xr = reinterpret_cast<const float4*>(x) + (size_t)row * (DIM / 4);

    float ss = 0.f;
    #pragma unroll
    for (int k = 0; k < 8; k++) {
        float4 v = xr[k * 32 + lane];
        ss += v.x * v.x + v.y * v.y + v.z * v.z + v.w * v.w;
    }
    #pragma unroll
    for (int o = 16; o; o >>= 1) ss += __shfl_xor_sync(0xffffffffu, ss, o);
    if (lane == 0) g_norm[row] = fmaxf(sqrtf(ss), 1e-8f);
}

// ---------------- main: 1 row/CTA, no reduction, flat quant chain ----------------
__global__ __launch_bounds__(TPB)
void planar_quant_kernel(const float* __restrict__ x,
                         const float* __restrict__ rot2,
                         float* __restrict__ out_xhat,
                         float* __restrict__ out_idx,
                         int write_idx) {
    __shared__ float2 lutf[NB];
    __shared__ int    luti[NB];
    __shared__ float2 tab[KCENT];

    const int t   = threadIdx.x;
    const int row = blockIdx.x;

    // ---- long-latency loads first ----
    const float4 xv   = reinterpret_cast<const float4*>(x + (size_t)row * DIM)[t];
    const float4 rv   = reinterpret_cast<const float4*>(rot2)[t];
    const float  norm = g_norm[row];
    const float scale = g_sb[0];
    const float bias  = g_sb[1];

    // ---- table copy: lutf 512 f4 (2/thr), luti 256 i4 (1/thr), tab 128 f4 ----
    reinterpret_cast<float4*>(lutf)[t]       = reinterpret_cast<const float4*>(g_lutf)[t];
    reinterpret_cast<float4*>(lutf)[t + TPB] = reinterpret_cast<const float4*>(g_lutf)[t + TPB];
    reinterpret_cast<int4*>(luti)[t]         = reinterpret_cast<const int4*>(g_luti)[t];
    if (t < KCENT / 2)
        reinterpret_cast<float4*>(tab)[t]    = reinterpret_cast<const float4*>(g_tab)[t];

    __syncthreads();   // single barrier: table visibility

    const float rn = 1.0f / norm;

    // ---- rotate ----
    const float v0 = xv.x * rn, v1 = xv.y * rn;
    const float v2 = xv.z * rn, v3 = xv.w * rn;
    const float r0 = rv.x * v0 - rv.y * v1;
    const float r1 = rv.y * v0 + rv.x * v1;
    const float r2 = rv.z * v2 - rv.w * v3;
    const float r3 = rv.w * v2 + rv.z * v3;

    // ---- quantize: parallel LUT fast path + exact walk ----
    auto quant = [&](float v, int& idx, float& q) {
        float bf = fmaf(v, scale, bias);
        int b = (int)fminf(fmaxf(bf, 0.0f), (float)(NB - 1));
        float2 f = lutf[b];      // (mid[i], cen[i])  — independent LDS
        int    i = luti[b];      //                    — independent LDS
        if (f.x >= v) { idx = i; q = f.y; return; }   // exact: i == argmin idx
        i++;
        float2 tc = tab[i];
        while (tc.x < v) { i++; tc = tab[i]; }        // mid[255]=+inf terminates
        idx = i; q = tc.y;
    };

    int   i0, i1, i2, i3;
    float q0, q1, q2, q3;
    quant(r0, i0, q0);
    quant(r1, i1, q1);
    quant(r2, i2, q2);
    quant(r3, i3, q3);

    // ---- inverse rotate, rescale, store ----
    float4 xh;
    xh.x = ( rv.x * q0 + rv.y * q1) * norm;
    xh.y = (-rv.y * q0 + rv.x * q1) * norm;
    xh.z = ( rv.z * q2 + rv.w * q3) * norm;
    xh.w = (-rv.w * q2 + rv.z * q3) * norm;
    reinterpret_cast<float4*>(out_xhat + (size_t)row * DIM)[t] = xh;

    if (write_idx) {
        float4 fi;
        fi.x = (float)i0; fi.y = (float)i1; fi.z = (float)i2; fi.w = (float)i3;
        reinterpret_cast<float4*>(out_idx + (size_t)row * DIM)[t] = fi;
    }
}

extern "C" void kernel_launch(void* const* d_in, const int* in_sizes, int n_in,
                              void* d_out, int out_size) {
    const float* x         = (const float*)d_in[0];  // [2048, 1024]
    const float* centroids = (const float*)d_in[1];  // [256]
    const float* rot2      = (const float*)d_in[2];  // [512, 2]

    float* out = (float*)d_out;
    const int full = (out_size >= 2 * NROWS * DIM);
    float* out_xhat = out;
    float* out_idx  = full ? out + (size_t)NROWS * DIM : out;

    prep_kernel<<<1, 256>>>(centroids);
    norm_kernel<<<NROWS / 8, 256>>>(x);          // 8 rows per CTA (warp/row)
    planar_quant_kernel<<<NROWS, TPB>>>(x, rot2, out_xhat, out_idx, full);
}

// round 8
// speedup vs baseline: 1.4551x; 1.4551x over previous
#include <cuda_runtime.h>
#include <math_constants.h>

#define NROWS 2048
#define DIM   1024
#define KCENT 256
#define NB    1024
#define TPB   256
#define PAD   16            // tab padding for bounded predicated probes

__device__ float2 g_tab[KCENT + PAD];  // (midpoint, centroid); mid[255..]=+inf
__device__ int    g_luti[NB];          // per-bin lower-bound index
__device__ float  g_sb[2];             // scale, bias
__device__ float  g_norm[NROWS];       // per-row norms

// ---------------- kernel A: LUT build (CTAs 0-3) + norms (CTAs 4-259) ----------------
__global__ __launch_bounds__(TPB)
void prep_norm_kernel(const float* __restrict__ x,
                      const float* __restrict__ centroids) {
    const int t = threadIdx.x;

    if (blockIdx.x < 4) {
        // ---- LUT builder: 4 CTAs x 256 threads = 1 bin/thread ----
        __shared__ float smid[KCENT];
        __shared__ int   sbin[KCENT];

        const float c0 = centroids[t];
        const float c1 = centroids[t < KCENT - 1 ? t + 1 : KCENT - 1];
        const float mid = (t < KCENT - 1) ? 0.5f * (c0 + c1) : CUDART_INF_F;
        smid[t] = mid;
        if (blockIdx.x == 0) {
            g_tab[t] = make_float2(mid, c0);
            if (t < PAD) g_tab[KCENT + t] = make_float2(CUDART_INF_F, 0.f);
        }
        __syncthreads();

        const float lo    = smid[0];
        const float hi    = smid[KCENT - 2];
        const float scale = (float)NB / fmaxf(hi - lo, 1e-30f);
        const float bias  = -lo * scale;
        if (blockIdx.x == 0 && t == 0) { g_sb[0] = scale; g_sb[1] = bias; }

        // bins of midpoints (sorted, since bin() is monotone)
        int mybin = 0x7fffffff;                 // sentinel for t = 255
        if (t < KCENT - 1) {
            float bf = fmaf(mid, scale, bias);
            mybin = (int)fminf(fmaxf(bf, 0.0f), (float)(NB - 1));
        }
        sbin[t] = mybin;
        __syncthreads();

        // luti[b] = lower_bound(sbin, b) = #{m : bin(m) < b}, 8-step branchless
        const int b = blockIdx.x * TPB + t;
        int pos = 0;
        #pragma unroll
        for (int s = 128; s; s >>= 1) {
            int np = pos + s;                   // <= 256? pos+s-1 <= 255
            if (sbin[np - 1] < b) pos = np;
        }
        g_luti[b] = pos;
    } else {
        // ---- norms: warp per row, 8 rows/CTA ----
        const int lane = t & 31;
        const int row  = (blockIdx.x - 4) * 8 + (t >> 5);
        const float4* __restrict__ xr =
            reinterpret_cast<const float4*>(x) + (size_t)row * (DIM / 4);

        float ss = 0.f;
        #pragma unroll
        for (int k = 0; k < 8; k++) {
            float4 v = xr[k * 32 + lane];
            ss += v.x * v.x + v.y * v.y + v.z * v.z + v.w * v.w;
        }
        #pragma unroll
        for (int o = 16; o; o >>= 1) ss += __shfl_xor_sync(0xffffffffu, ss, o);
        if (lane == 0) g_norm[row] = fmaxf(sqrtf(ss), 1e-8f);
    }
}

// ---------------- kernel B: 2 rows/CTA, branchless quant, one barrier ----------------
__global__ __launch_bounds__(TPB, 6)
void planar_quant_kernel(const float* __restrict__ x,
                         const float* __restrict__ rot2,
                         float* __restrict__ out_xhat,
                         float* __restrict__ out_idx,
                         int write_idx) {
    __shared__ float2 tab[KCENT + PAD];
    __shared__ int    luti[NB];

    const int t    = threadIdx.x;
    const int rowA = blockIdx.x * 2;
    const int rowB = rowA + 1;

    // ---- long-latency loads first ----
    const float4 xvA = reinterpret_cast<const float4*>(x + (size_t)rowA * DIM)[t];
    const float4 xvB = reinterpret_cast<const float4*>(x + (size_t)rowB * DIM)[t];
    const float4 rv  = reinterpret_cast<const float4*>(rot2)[t];
    const float normA = g_norm[rowA];
    const float normB = g_norm[rowB];
    const float scale = g_sb[0];
    const float bias  = g_sb[1];

    // ---- table copy: luti 256 int4 (1/thr), tab 136 float4 ----
    reinterpret_cast<int4*>(luti)[t] = reinterpret_cast<const int4*>(g_luti)[t];
    if (t < (KCENT + PAD) / 2)
        reinterpret_cast<float4*>(tab)[t] = reinterpret_cast<const float4*>(g_tab)[t];

    __syncthreads();   // single barrier: table visibility

    const float rnA = 1.0f / normA;
    const float rnB = 1.0f / normB;

    // branchless quant: lower bound + 4 predicated binary steps (covers offset <= 15)
    auto quant = [&](float v, int& idx, float& q) {
        float bf = fmaf(v, scale, bias);
        int b = (int)fminf(fmaxf(bf, 0.0f), (float)(NB - 1));
        int i = luti[b];
        i += (tab[i + 7].x < v) ? 8 : 0;
        i += (tab[i + 3].x < v) ? 4 : 0;
        i += (tab[i + 1].x < v) ? 2 : 0;
        i += (tab[i].x     < v) ? 1 : 0;
        idx = i;
        q = tab[i].y;
    };

    #pragma unroll
    for (int r = 0; r < 2; r++) {
        const float4 xv  = r ? xvB : xvA;
        const float  rn  = r ? rnB : rnA;
        const float  nrm = r ? normB : normA;
        const int    row = r ? rowB : rowA;

        const float v0 = xv.x * rn, v1 = xv.y * rn;
        const float v2 = xv.z * rn, v3 = xv.w * rn;
        const float r0 = rv.x * v0 - rv.y * v1;
        const float r1 = rv.y * v0 + rv.x * v1;
        const float r2 = rv.z * v2 - rv.w * v3;
        const float r3 = rv.w * v2 + rv.z * v3;

        int   i0, i1, i2, i3;
        float q0, q1, q2, q3;
        quant(r0, i0, q0);
        quant(r1, i1, q1);
        quant(r2, i2, q2);
        quant(r3, i3, q3);

        float4 xh;
        xh.x = ( rv.x * q0 + rv.y * q1) * nrm;
        xh.y = (-rv.y * q0 + rv.x * q1) * nrm;
        xh.z = ( rv.z * q2 + rv.w * q3) * nrm;
        xh.w = (-rv.w * q2 + rv.z * q3) * nrm;
        reinterpret_cast<float4*>(out_xhat + (size_t)row * DIM)[t] = xh;

        if (write_idx) {
            float4 fi;
            fi.x = (float)i0; fi.y = (float)i1; fi.z = (float)i2; fi.w = (float)i3;
            reinterpret_cast<float4*>(out_idx + (size_t)row * DIM)[t] = fi;
        }
    }
}

extern "C" void kernel_launch(void* const* d_in, const int* in_sizes, int n_in,
                              void* d_out, int out_size) {
    const float* x         = (const float*)d_in[0];  // [2048, 1024]
    const float* centroids = (const float*)d_in[1];  // [256]
    const float* rot2      = (const float*)d_in[2];  // [512, 2]

    float* out = (float*)d_out;
    const int full = (out_size >= 2 * NROWS * DIM);
    float* out_xhat = out;
    float* out_idx  = full ? out + (size_t)NROWS * DIM : out;

    prep_norm_kernel<<<4 + NROWS / 8, TPB>>>(x, centroids);
    planar_quant_kernel<<<NROWS / 2, TPB>>>(x, rot2, out_xhat, out_idx, full);
}